// round 12
// baseline (speedup 1.0000x reference)
#include <cuda_runtime.h>
#include <cuda_fp16.h>
#include <cstdint>

#define H_IN   224
#define H_OUT  220
#define C_IN   32
#define N_FILT 64
#define KS     5
#define NTAP   25
#define BATCH  16

#define TR 16
#define TC 32
#define HR 20
#define HC 36
#define NLINES (HR * HC)            // 720
#define NTX 7
#define NTY 14
#define NTILES (NTX * NTY * BATCH)  // 1568

#define ASTRIDE 80
#define HALO_BYTES (NLINES * ASTRIDE)        // 57600
#define B_TILE  4096
#define B_OFF   (2 * HALO_BYTES)             // 115200
#define SMEM_BYTES (B_OFF + NTAP * B_TILE)   // 217600

__device__ __half g_wf[NTAP * 2048];

// ---------------- helpers ----------------
__device__ __forceinline__ uint32_t smem_u32(const void* p) {
    uint32_t a;
    asm("{ .reg .u64 t; cvta.to.shared.u64 t, %1; cvt.u32.u64 %0, t; }" : "=r"(a) : "l"(p));
    return a;
}
__device__ __forceinline__ void cpa16(uint32_t s, const void* g) {
    asm volatile("cp.async.ca.shared.global [%0], [%1], 16;" :: "r"(s), "l"(g));
}
__device__ __forceinline__ void cp_commit() { asm volatile("cp.async.commit_group;"); }
__device__ __forceinline__ void cp_wait0()  { asm volatile("cp.async.wait_group 0;"); }

__device__ __forceinline__ void ldsm4(uint32_t* r, uint32_t a) {
    asm volatile("ldmatrix.sync.aligned.m8n8.x4.shared.b16 {%0,%1,%2,%3}, [%4];"
                 : "=r"(r[0]), "=r"(r[1]), "=r"(r[2]), "=r"(r[3]) : "r"(a));
}
__device__ __forceinline__ void ldsv4(uint32_t* r, uint32_t a) {
    asm volatile("ld.shared.v4.u32 {%0,%1,%2,%3}, [%4];"
                 : "=r"(r[0]), "=r"(r[1]), "=r"(r[2]), "=r"(r[3]) : "r"(a));
}
__device__ __forceinline__ void mma16816(float* d, const uint32_t* a,
                                         uint32_t b0, uint32_t b1) {
    asm volatile(
        "mma.sync.aligned.m16n8k16.row.col.f32.f16.f16.f32 "
        "{%0,%1,%2,%3}, {%4,%5,%6,%7}, {%8,%9}, {%0,%1,%2,%3};"
        : "+f"(d[0]), "+f"(d[1]), "+f"(d[2]), "+f"(d[3])
        : "r"(a[0]), "r"(a[1]), "r"(a[2]), "r"(a[3]), "r"(b0), "r"(b1));
}
__device__ __forceinline__ void sts16(uint32_t a, unsigned short v) {
    asm volatile("st.shared.u16 [%0], %1;" :: "r"(a), "h"(v));
}

// ---------------- prep: weights -> fp16 in mma-fragment order ----------------
__global__ void prep_weights(const float* __restrict__ w) {
    int idx = blockIdx.x * blockDim.x + threadIdx.x;
    if (idx >= NTAP * 1024) return;
    int tap = idx >> 10;
    int rem = idx & 1023;
    int grp  = rem >> 7;
    int lane = (rem >> 2) & 31;
    int r    = rem & 3;
    int ks = grp >> 2, np = grp & 3;
    int c = ks * 16 + (lane & 3) * 2 + ((r & 1) ? 8 : 0);
    int f = np * 16 + (lane >> 2)   + ((r & 2) ? 8 : 0);
    __half h0 = __float2half(w[(f * C_IN + c    ) * (KS * KS) + tap]);
    __half h1 = __float2half(w[(f * C_IN + c + 1) * (KS * KS) + tap]);
    __half2* dst = reinterpret_cast<__half2*>(g_wf + (size_t)tap * 2048);
    dst[rem] = __halves2half2(h0, h1);
}

// ---------------- main kernel (persistent) ----------------
__global__ __launch_bounds__(256, 1)
void conv_mma_kernel(const float* __restrict__ x,
                     const float* __restrict__ bias,
                     float* __restrict__ out)
{
    extern __shared__ __align__(128) char smem[];
    const uint32_t sb = smem_u32(smem);

    const int tid = threadIdx.x;
    const int wid = tid >> 5, lid = tid & 31;
    const int g = lid >> 2, c4 = lid & 3;
    const int lrow = lid & 15;
    const int lcol = lid >> 4;

    // ---- stage ALL B tiles ONCE (100KB, async) ----
    #pragma unroll
    for (int j = 0; j < 25; ++j)
        cpa16(sb + B_OFF + (tid + j * 256) * 16, g_wf + ((size_t)tid + j * 256) * 8);
    cp_commit();

    int tile = blockIdx.x;
    if (tile >= NTILES) return;

    // ---- full halo convert for the FIRST tile into buffer 0 ----
    {
        int tx = tile % NTX, tmp = tile / NTX;
        int ty = tmp % NTY, b = tmp / NTY;
        int x0 = tx * TC, y0 = ty * TR;
        const float* xb = x + (size_t)b * C_IN * H_IN * H_IN;
        #pragma unroll 1
        for (int j = 0; j < 90; ++j) {          // 90*256 = 23040 = 720*32
            int e = j * 256 + tid;
            int c = e / NLINES;
            int line = e - c * NLINES;
            int hy = line / HC, hx = line - hy * HC;
            int gy = y0 + hy, gx = x0 + hx;
            float v = (gy < H_IN && gx < H_IN)
                    ? xb[(size_t)c * H_IN * H_IN + (size_t)gy * H_IN + gx] : 0.0f;
            sts16(sb + line * ASTRIDE + c * 2, __half_as_ushort(__float2half(v)));
        }
    }
    cp_wait0();
    __syncthreads();

    int buf = 0;

    #pragma unroll 1
    for (; tile < NTILES; tile += gridDim.x) {
        // current tile coords
        int tx = tile % NTX, tmp = tile / NTX;
        int ty = tmp % NTY, b = tmp / NTY;
        const int x0 = tx * TC, y0 = ty * TR;

        // next tile coords (for halo prefetch-convert)
        const int ntile = tile + gridDim.x;
        const bool has_next = ntile < NTILES;
        int nx0 = 0, ny0 = 0;
        const float* nxb = x;
        if (has_next) {
            int ntx = ntile % NTX, ntmp = ntile / NTX;
            int nty = ntmp % NTY, nb = ntmp / NTY;
            nx0 = ntx * TC; ny0 = nty * TR;
            nxb = x + (size_t)nb * C_IN * H_IN * H_IN;
        }

        float acc[4][8][4];
        #pragma unroll
        for (int mb = 0; mb < 4; ++mb)
            #pragma unroll
            for (int ns = 0; ns < 8; ++ns)
                #pragma unroll
                for (int q = 0; q < 4; ++q) acc[mb][ns][q] = 0.0f;

        const uint32_t hbase = sb + buf * HALO_BYTES;
        const uint32_t nbase = sb + (buf ^ 1) * HALO_BYTES;
        const uint32_t a_base = hbase + (uint32_t)((2 * wid * HC + lrow) * ASTRIDE)
                              + lcol * 16;
        const uint32_t b_base0 = sb + B_OFF + lid * 16;

        #pragma unroll 1
        for (int t = 0; t < NTAP; ++t) {
            const int kh = (t * 52) >> 8;
            const int kw = t - kh * 5;
            const uint32_t a_t = a_base + (uint32_t)((kh * HC + kw) * ASTRIDE);
            const uint32_t b_t = b_base0 + (uint32_t)t * B_TILE;

            // whole-tap load batch
            uint32_t afr[2][4][4];
            uint32_t bq[2][4][4];
            #pragma unroll
            for (int kk = 0; kk < 2; ++kk) {
                ldsm4(afr[kk][0], a_t + kk * 32);
                ldsm4(afr[kk][1], a_t + 16 * ASTRIDE + kk * 32);
                ldsm4(afr[kk][2], a_t + HC * ASTRIDE + kk * 32);
                ldsm4(afr[kk][3], a_t + (HC + 16) * ASTRIDE + kk * 32);
            }
            #pragma unroll
            for (int kk = 0; kk < 2; ++kk)
                #pragma unroll
                for (int np = 0; np < 4; ++np)
                    ldsv4(bq[kk][np], b_t + (kk * 4 + np) * 512);

            // prefetch-convert 30 halo lines of the NEXT tile (taps 0..23)
            if (has_next && t < 24) {
                const int L0 = t * 30;
                #pragma unroll
                for (int k = 0; k < 4; ++k) {
                    int e = k * 256 + tid;
                    if (e < 960) {
                        int c = e / 30;
                        int dl = e - c * 30;
                        int line = L0 + dl;
                        int hy = line / HC, hx = line - hy * HC;
                        int gy = ny0 + hy, gx = nx0 + hx;
                        float v = (gy < H_IN && gx < H_IN)
                                ? nxb[(size_t)c * H_IN * H_IN + (size_t)gy * H_IN + gx]
                                : 0.0f;
                        sts16(nbase + line * ASTRIDE + c * 2,
                              __half_as_ushort(__float2half(v)));
                    }
                }
            }

            #pragma unroll
            for (int kk = 0; kk < 2; ++kk) {
                #pragma unroll
                for (int np = 0; np < 4; ++np) {
                    #pragma unroll
                    for (int mb = 0; mb < 4; ++mb) {
                        mma16816(acc[mb][2 * np + 0], afr[kk][mb], bq[kk][np][0], bq[kk][np][1]);
                        mma16816(acc[mb][2 * np + 1], afr[kk][mb], bq[kk][np][2], bq[kk][np][3]);
                    }
                }
            }
        }

        // ---- epilogue (regs only; no smem) ----
        #pragma unroll
        for (int mb = 0; mb < 4; ++mb) {
            const int oy = y0 + 2 * wid + (mb >> 1);
            if (oy >= H_OUT) continue;
            #pragma unroll
            for (int h = 0; h < 2; ++h) {
                const int ox = x0 + (mb & 1) * 16 + h * 8 + g;
                if (ox >= H_OUT) continue;
                size_t base = (((size_t)b * N_FILT) * H_OUT + oy) * H_OUT + ox;
                #pragma unroll
                for (int ns = 0; ns < 8; ++ns) {
                    int f = ns * 8 + 2 * c4;
                    out[base + (size_t)f * H_OUT * H_OUT] =
                        acc[mb][ns][2 * h + 0] + bias[f];
                    out[base + (size_t)(f + 1) * H_OUT * H_OUT] =
                        acc[mb][ns][2 * h + 1] + bias[f + 1];
                }
            }
        }

        __syncthreads();   // halo buffer handoff
        buf ^= 1;
    }
}

extern "C" void kernel_launch(void* const* d_in, const int* in_sizes, int n_in,
                              void* d_out, int out_size) {
    const float* x    = (const float*)d_in[0];
    const float* w    = (const float*)d_in[1];
    const float* bias = (const float*)d_in[2];
    float* out = (float*)d_out;

    cudaFuncSetAttribute(conv_mma_kernel,
                         cudaFuncAttributeMaxDynamicSharedMemorySize, SMEM_BYTES);

    prep_weights<<<(NTAP * 1024 + 255) / 256, 256>>>(w);

    int dev = 0, nsm = 148;
    cudaGetDevice(&dev);
    cudaDeviceGetAttribute(&nsm, cudaDevAttrMultiProcessorCount, dev);

    conv_mma_kernel<<<nsm, 256, SMEM_BYTES>>>(x, bias, out);
}

// round 15
// speedup vs baseline: 1.5500x; 1.5500x over previous
#include <cuda_runtime.h>
#include <cuda_fp16.h>
#include <cstdint>

#define H_IN   224
#define H_OUT  220
#define C_IN   32
#define N_FILT 64
#define KS     5
#define NTAP   25
#define BATCH  16

#define TR 16
#define TC 32
#define HR 20
#define HC 36
#define NLINES (HR * HC)   // 720
#define NTX 7
#define NTY 14

#define ASTRIDE 80
#define A_BYTES (NLINES * ASTRIDE)          // 57600
#define B_TILE  4096
#define B_OFF   A_BYTES
#define SMEM_BYTES (B_OFF + NTAP * B_TILE)  // 160000

// epilogue smem buffer (reuses halo+B space after mainloop):
// [f][row][x] fp32, f-stride 532 words, row-stride 33 words
#define EP_FSTR 532
#define EP_RSTR 33

__device__ __half g_wf[NTAP * 2048];

// ---------------- helpers ----------------
__device__ __forceinline__ uint32_t smem_u32(const void* p) {
    uint32_t a;
    asm("{ .reg .u64 t; cvta.to.shared.u64 t, %1; cvt.u32.u64 %0, t; }" : "=r"(a) : "l"(p));
    return a;
}
__device__ __forceinline__ void cpa16(uint32_t s, const void* g) {
    asm volatile("cp.async.ca.shared.global [%0], [%1], 16;" :: "r"(s), "l"(g));
}
__device__ __forceinline__ void cp_commit() { asm volatile("cp.async.commit_group;"); }
__device__ __forceinline__ void cp_wait0()  { asm volatile("cp.async.wait_group 0;"); }

__device__ __forceinline__ void ldsm4(uint32_t* r, uint32_t a) {
    asm volatile("ldmatrix.sync.aligned.m8n8.x4.shared.b16 {%0,%1,%2,%3}, [%4];"
                 : "=r"(r[0]), "=r"(r[1]), "=r"(r[2]), "=r"(r[3]) : "r"(a));
}
__device__ __forceinline__ void ldsv4(uint32_t* r, uint32_t a) {
    asm volatile("ld.shared.v4.u32 {%0,%1,%2,%3}, [%4];"
                 : "=r"(r[0]), "=r"(r[1]), "=r"(r[2]), "=r"(r[3]) : "r"(a));
}
__device__ __forceinline__ void mma16816(float* d, const uint32_t* a,
                                         uint32_t b0, uint32_t b1) {
    asm volatile(
        "mma.sync.aligned.m16n8k16.row.col.f32.f16.f16.f32 "
        "{%0,%1,%2,%3}, {%4,%5,%6,%7}, {%8,%9}, {%0,%1,%2,%3};"
        : "+f"(d[0]), "+f"(d[1]), "+f"(d[2]), "+f"(d[3])
        : "r"(a[0]), "r"(a[1]), "r"(a[2]), "r"(a[3]), "r"(b0), "r"(b1));
}
__device__ __forceinline__ void sts32(uint32_t a, uint32_t v) {
    asm volatile("st.shared.b32 [%0], %1;" :: "r"(a), "r"(v));
}

// ---------------- prep: weights -> fp16 in mma-fragment order ----------------
__global__ void prep_weights(const float* __restrict__ w) {
    int idx = blockIdx.x * blockDim.x + threadIdx.x;
    if (idx >= NTAP * 1024) return;
    int tap = idx >> 10;
    int rem = idx & 1023;
    int grp  = rem >> 7;
    int lane = (rem >> 2) & 31;
    int r    = rem & 3;
    int ks = grp >> 2, np = grp & 3;
    int c = ks * 16 + (lane & 3) * 2 + ((r & 1) ? 8 : 0);
    int f = np * 16 + (lane >> 2)   + ((r & 2) ? 8 : 0);
    __half h0 = __float2half(w[(f * C_IN + c    ) * (KS * KS) + tap]);
    __half h1 = __float2half(w[(f * C_IN + c + 1) * (KS * KS) + tap]);
    __half2* dst = reinterpret_cast<__half2*>(g_wf + (size_t)tap * 2048);
    dst[rem] = __halves2half2(h0, h1);
}

// ---------------- main kernel ----------------
__global__ __launch_bounds__(256, 1)
void conv_mma_kernel(const float* __restrict__ x,
                     const float* __restrict__ bias,
                     float* __restrict__ out)
{
    extern __shared__ __align__(128) char smem[];
    const uint32_t sb = smem_u32(smem);

    const int tid = threadIdx.x;
    const int wid = tid >> 5, lid = tid & 31;
    const int g = lid >> 2, c4 = lid & 3;

    const int x0 = blockIdx.x * TC;
    const int y0 = blockIdx.y * TR;
    const int b  = blockIdx.z;

    // ---- stage ALL B tiles (100KB, async) ----
    #pragma unroll
    for (int j = 0; j < 25; ++j)
        cpa16(sb + B_OFF + (tid + j * 256) * 16, g_wf + ((size_t)tid + j * 256) * 8);
    cp_commit();

    // ---- build A halo: chunk-XOR swizzled, conflict-free STS.32 ----
    {
        const float* xb = x + (size_t)b * C_IN * H_IN * H_IN;
        #pragma unroll 1
        for (int j = 0; j < 3; ++j) {
            int line = tid + j * 256;
            if (line < NLINES) {
                int hy = line / HC, hx = line - hy * HC;
                int gy = y0 + hy, gx = x0 + hx;
                const bool ok = (gy < H_IN) && (gx < H_IN);
                const float* p = xb + (size_t)gy * H_IN + gx;
                const uint32_t lbase = sb + line * ASTRIDE;
                const uint32_t swl = (((uint32_t)line >> 3) & 3) << 4;
                #pragma unroll
                for (int cp = 0; cp < 16; ++cp) {
                    float v0 = ok ? p[(size_t)(2 * cp    ) * (H_IN * H_IN)] : 0.0f;
                    float v1 = ok ? p[(size_t)(2 * cp + 1) * (H_IN * H_IN)] : 0.0f;
                    __half2 h = __floats2half2_rn(v0, v1);
                    uint32_t addr = lbase
                                  + (((((uint32_t)cp >> 2) << 4)) ^ swl)
                                  + (cp & 3) * 4;
                    sts32(addr, *reinterpret_cast<uint32_t*>(&h));
                }
            }
        }
    }
    cp_wait0();
    __syncthreads();

    float acc[4][8][4];
    #pragma unroll
    for (int mb = 0; mb < 4; ++mb)
        #pragma unroll
        for (int ns = 0; ns < 8; ++ns)
            #pragma unroll
            for (int q = 0; q < 4; ++q) acc[mb][ns][q] = 0.0f;

    const int lrow = lid & 15;
    const int lcol = lid >> 4;
    const int lineoff[4] = { lrow, lrow + 16, lrow + HC, lrow + HC + 16 };
    const uint32_t b_base0 = sb + B_OFF + lid * 16;

    const int start = wid * 3;

    #pragma unroll 1
    for (int t = 0; t < NTAP; ++t) {
        int tap = t + start;
        if (tap >= NTAP) tap -= NTAP;
        const int kh = (tap * 52) >> 8;
        const int kw = tap - kh * 5;
        const int L0 = (2 * wid + kh) * HC + kw;
        const uint32_t b_t = b_base0 + (uint32_t)tap * B_TILE;

        // whole-tap load batch: 8 ldsm (swizzled) + 8 ldsv4, then 64 mma
        uint32_t afr[2][4][4];
        uint32_t bq[2][4][4];
        #pragma unroll
        for (int mb = 0; mb < 4; ++mb) {
            const int ln = L0 + lineoff[mb];
            const uint32_t sw = (((uint32_t)ln >> 3) & 3);
            const uint32_t base = sb + (uint32_t)ln * ASTRIDE;
            ldsm4(afr[0][mb], base + (((uint32_t)lcol       ^ sw) << 4));
            ldsm4(afr[1][mb], base + (((uint32_t)(lcol + 2) ^ sw) << 4));
        }
        #pragma unroll
        for (int kk = 0; kk < 2; ++kk)
            #pragma unroll
            for (int np = 0; np < 4; ++np)
                ldsv4(bq[kk][np], b_t + (kk * 4 + np) * 512);

        #pragma unroll
        for (int kk = 0; kk < 2; ++kk) {
            #pragma unroll
            for (int np = 0; np < 4; ++np) {
                #pragma unroll
                for (int mb = 0; mb < 4; ++mb) {
                    mma16816(acc[mb][2 * np + 0], afr[kk][mb], bq[kk][np][0], bq[kk][np][1]);
                    mma16816(acc[mb][2 * np + 1], afr[kk][mb], bq[kk][np][2], bq[kk][np][3]);
                }
            }
        }
    }

    // ---- epilogue: smem bounce -> coalesced STG.32 rows ----
    __syncthreads();   // all warps done reading halo/B before overwrite

    {
        const int row0 = 2 * wid;
        #pragma unroll
        for (int mb = 0; mb < 4; ++mb) {
            const int row = row0 + (mb >> 1);
            const int xx  = (mb & 1) * 16 + g;
            #pragma unroll
            for (int ns = 0; ns < 8; ++ns) {
                #pragma unroll
                for (int q = 0; q < 4; ++q) {
                    const int h = q >> 1, pp = q & 1;
                    const int f = ns * 8 + 2 * c4 + pp;
                    const uint32_t wrd = (uint32_t)(f * EP_FSTR + row * EP_RSTR + xx + h * 8);
                    asm volatile("st.shared.f32 [%0], %1;"
                                 :: "r"(sb + wrd * 4), "f"(acc[mb][ns][q]));
                }
            }
        }
    }
    __syncthreads();

    {
        #pragma unroll 4
        for (int i = 0; i < 128; ++i) {
            const int idx = wid * 128 + i;
            const int f = idx >> 4, row = idx & 15;
            const int oy = y0 + row, ox = x0 + lid;
            float v;
            asm volatile("ld.shared.f32 %0, [%1];" : "=f"(v)
                         : "r"(sb + (uint32_t)(f * EP_FSTR + row * EP_RSTR + lid) * 4));
            if (oy < H_OUT && ox < H_OUT)
                out[(((size_t)b * N_FILT + f) * H_OUT + oy) * H_OUT + ox] = v + bias[f];
        }
    }
}

extern "C" void kernel_launch(void* const* d_in, const int* in_sizes, int n_in,
                              void* d_out, int out_size) {
    const float* x    = (const float*)d_in[0];
    const float* w    = (const float*)d_in[1];
    const float* bias = (const float*)d_in[2];
    float* out = (float*)d_out;

    cudaFuncSetAttribute(conv_mma_kernel,
                         cudaFuncAttributeMaxDynamicSharedMemorySize, SMEM_BYTES);

    prep_weights<<<(NTAP * 1024 + 255) / 256, 256>>>(w);

    dim3 grid(NTX, NTY, BATCH);
    conv_mma_kernel<<<grid, 256, SMEM_BYTES>>>(x, bias, out);
}

// round 16
// speedup vs baseline: 1.5854x; 1.0228x over previous
#include <cuda_runtime.h>
#include <cuda_fp16.h>
#include <cstdint>

#define H_IN   224
#define H_OUT  220
#define C_IN   32
#define N_FILT 64
#define KS     5
#define NTAP   25
#define BATCH  16

#define TR 16
#define TC 32
#define HR 20
#define HC 36
#define NLINES (HR * HC)   // 720
#define NTX 7
#define NTY 14
#define NTILES (NTX * NTY * BATCH)   // 1568

#define ASTRIDE 80
#define A_BYTES (NLINES * ASTRIDE)          // 57600
#define B_TILE  4096
#define B_OFF   A_BYTES
#define SMEM_BYTES (B_OFF + NTAP * B_TILE)  // 160000

__device__ __half g_wf[NTAP * 2048];                       // weights, frag order
__device__ __align__(16) __half g_xt[(size_t)NTILES * NLINES * C_IN];  // 72MB pre-tiled halo

// ---------------- helpers ----------------
__device__ __forceinline__ uint32_t smem_u32(const void* p) {
    uint32_t a;
    asm("{ .reg .u64 t; cvta.to.shared.u64 t, %1; cvt.u32.u64 %0, t; }" : "=r"(a) : "l"(p));
    return a;
}
__device__ __forceinline__ void cpa16(uint32_t s, const void* g) {
    asm volatile("cp.async.ca.shared.global [%0], [%1], 16;" :: "r"(s), "l"(g));
}
__device__ __forceinline__ void cp_commit() { asm volatile("cp.async.commit_group;"); }
__device__ __forceinline__ void cp_wait0()  { asm volatile("cp.async.wait_group 0;"); }

__device__ __forceinline__ void ldsm4(uint32_t* r, uint32_t a) {
    asm volatile("ldmatrix.sync.aligned.m8n8.x4.shared.b16 {%0,%1,%2,%3}, [%4];"
                 : "=r"(r[0]), "=r"(r[1]), "=r"(r[2]), "=r"(r[3]) : "r"(a));
}
__device__ __forceinline__ void ldsv4(uint32_t* r, uint32_t a) {
    asm volatile("ld.shared.v4.u32 {%0,%1,%2,%3}, [%4];"
                 : "=r"(r[0]), "=r"(r[1]), "=r"(r[2]), "=r"(r[3]) : "r"(a));
}
__device__ __forceinline__ void mma16816(float* d, const uint32_t* a,
                                         uint32_t b0, uint32_t b1) {
    asm volatile(
        "mma.sync.aligned.m16n8k16.row.col.f32.f16.f16.f32 "
        "{%0,%1,%2,%3}, {%4,%5,%6,%7}, {%8,%9}, {%0,%1,%2,%3};"
        : "+f"(d[0]), "+f"(d[1]), "+f"(d[2]), "+f"(d[3])
        : "r"(a[0]), "r"(a[1]), "r"(a[2]), "r"(a[3]), "r"(b0), "r"(b1));
}

// ---------------- prep 1: weights -> fp16 in mma-fragment order ----------------
__global__ void prep_weights(const float* __restrict__ w) {
    int idx = blockIdx.x * blockDim.x + threadIdx.x;
    if (idx >= NTAP * 1024) return;
    int tap = idx >> 10;
    int rem = idx & 1023;
    int grp  = rem >> 7;
    int lane = (rem >> 2) & 31;
    int r    = rem & 3;
    int ks = grp >> 2, np = grp & 3;
    int c = ks * 16 + (lane & 3) * 2 + ((r & 1) ? 8 : 0);
    int f = np * 16 + (lane >> 2)   + ((r & 2) ? 8 : 0);
    __half h0 = __float2half(w[(f * C_IN + c    ) * (KS * KS) + tap]);
    __half h1 = __float2half(w[(f * C_IN + c + 1) * (KS * KS) + tap]);
    __half2* dst = reinterpret_cast<__half2*>(g_wf + (size_t)tap * 2048);
    dst[rem] = __halves2half2(h0, h1);
}

// ---------------- prep 2: x -> fp16 pre-tiled halos [tile][line][c] ----------------
__global__ __launch_bounds__(256)
void prep_halos(const float* __restrict__ x) {
    const int tile = blockIdx.x;
    const int tid  = threadIdx.x;
    const int tx = tile % NTX;
    int tmp = tile / NTX;
    const int ty = tmp % NTY, b = tmp / NTY;
    const int x0 = tx * TC, y0 = ty * TR;
    const float* xb = x + (size_t)b * C_IN * H_IN * H_IN;
    __half* dst_t = g_xt + (size_t)tile * (NLINES * C_IN);

    #pragma unroll
    for (int j = 0; j < 3; ++j) {
        int line = tid + j * 256;
        if (line >= NLINES) break;
        int hy = line / HC, hx = line - hy * HC;
        int gy = y0 + hy, gx = x0 + hx;
        const bool ok = (gy < H_IN) && (gx < H_IN);
        const float* p = xb + (size_t)gy * H_IN + gx;
        __half2 h[16];
        #pragma unroll
        for (int cp = 0; cp < 16; ++cp) {
            float v0 = ok ? p[(size_t)(2 * cp    ) * (H_IN * H_IN)] : 0.0f;
            float v1 = ok ? p[(size_t)(2 * cp + 1) * (H_IN * H_IN)] : 0.0f;
            h[cp] = __floats2half2_rn(v0, v1);
        }
        uint4* d = reinterpret_cast<uint4*>(dst_t + (size_t)line * C_IN);
        const uint4* s = reinterpret_cast<const uint4*>(h);
        d[0] = s[0]; d[1] = s[1]; d[2] = s[2]; d[3] = s[3];
    }
}

// ---------------- main kernel ----------------
__global__ __launch_bounds__(256, 1)
void conv_mma_kernel(const float* __restrict__ bias,
                     float* __restrict__ out)
{
    extern __shared__ __align__(128) char smem[];
    const uint32_t sb = smem_u32(smem);

    const int tid = threadIdx.x;
    const int wid = tid >> 5, lid = tid & 31;
    const int g = lid >> 2, c4 = lid & 3;

    const int x0 = blockIdx.x * TC;
    const int y0 = blockIdx.y * TR;
    const int b  = blockIdx.z;
    const int tile = (b * NTY + blockIdx.y) * NTX + blockIdx.x;

    // ---- stage ALL B tiles (100KB) + halo (45KB) via cp.async, one wait ----
    #pragma unroll
    for (int j = 0; j < 25; ++j)
        cpa16(sb + B_OFF + (tid + j * 256) * 16, g_wf + ((size_t)tid + j * 256) * 8);
    {
        const __half* src_t = g_xt + (size_t)tile * (NLINES * C_IN);
        #pragma unroll
        for (int j = 0; j < 12; ++j) {
            int idx = tid + j * 256;              // 2880 chunks of 16B
            if (idx < NLINES * 4) {
                int line = idx >> 2, ch = idx & 3;
                cpa16(sb + line * ASTRIDE + ch * 16,
                      src_t + (size_t)line * C_IN + ch * 8);
            }
        }
    }
    cp_commit();
    cp_wait0();
    __syncthreads();      // the ONLY barrier

    float acc[4][8][4];
    #pragma unroll
    for (int mb = 0; mb < 4; ++mb)
        #pragma unroll
        for (int ns = 0; ns < 8; ++ns)
            #pragma unroll
            for (int q = 0; q < 4; ++q) acc[mb][ns][q] = 0.0f;

    const int lrow = lid & 15;
    const int lcol = lid >> 4;
    const uint32_t a_base = sb + (uint32_t)((2 * wid * HC + lrow) * ASTRIDE) + lcol * 16;
    const uint32_t b_base0 = sb + B_OFF + lid * 16;

    #pragma unroll 1
    for (int kh = 0; kh < 5; ++kh) {
        const uint32_t a_kh = a_base + (uint32_t)(kh * HC * ASTRIDE);
        const uint32_t b_kh = b_base0 + (uint32_t)(kh * 5) * B_TILE;
        #pragma unroll
        for (int kw = 0; kw < 5; ++kw) {
            const uint32_t a_t = a_kh + (uint32_t)(kw * ASTRIDE);
            const uint32_t b_t = b_kh + (uint32_t)kw * B_TILE;

            // whole-tap load batch: 8 ldsm + 8 ldsv4, then 64 mma
            uint32_t afr[2][4][4];
            uint32_t bq[2][4][4];
            #pragma unroll
            for (int kk = 0; kk < 2; ++kk) {
                ldsm4(afr[kk][0], a_t + kk * 32);
                ldsm4(afr[kk][1], a_t + 16 * ASTRIDE + kk * 32);
                ldsm4(afr[kk][2], a_t + HC * ASTRIDE + kk * 32);
                ldsm4(afr[kk][3], a_t + (HC + 16) * ASTRIDE + kk * 32);
            }
            #pragma unroll
            for (int kk = 0; kk < 2; ++kk)
                #pragma unroll
                for (int np = 0; np < 4; ++np)
                    ldsv4(bq[kk][np], b_t + (kk * 4 + np) * 512);

            #pragma unroll
            for (int kk = 0; kk < 2; ++kk) {
                #pragma unroll
                for (int np = 0; np < 4; ++np) {
                    #pragma unroll
                    for (int mb = 0; mb < 4; ++mb) {
                        mma16816(acc[mb][2 * np + 0], afr[kk][mb], bq[kk][np][0], bq[kk][np][1]);
                        mma16816(acc[mb][2 * np + 1], afr[kk][mb], bq[kk][np][2], bq[kk][np][3]);
                    }
                }
            }
        }
    }

    // ---- epilogue (r10-proven) ----
    float bv[8][2];
    #pragma unroll
    for (int ns = 0; ns < 8; ++ns) {
        bv[ns][0] = bias[ns * 8 + 2 * c4];
        bv[ns][1] = bias[ns * 8 + 2 * c4 + 1];
    }

    #pragma unroll
    for (int mb = 0; mb < 4; ++mb) {
        const int oy = y0 + 2 * wid + (mb >> 1);
        if (oy >= H_OUT) continue;
        #pragma unroll
        for (int h = 0; h < 2; ++h) {
            const int ox = x0 + (mb & 1) * 16 + h * 8 + g;
            if (ox >= H_OUT) continue;
            size_t base = (((size_t)b * N_FILT) * H_OUT + oy) * H_OUT + ox;
            #pragma unroll
            for (int ns = 0; ns < 8; ++ns) {
                int f = ns * 8 + 2 * c4;
                out[base + (size_t)f * H_OUT * H_OUT] =
                    acc[mb][ns][2 * h + 0] + bv[ns][0];
                out[base + (size_t)(f + 1) * H_OUT * H_OUT] =
                    acc[mb][ns][2 * h + 1] + bv[ns][1];
            }
        }
    }
}

extern "C" void kernel_launch(void* const* d_in, const int* in_sizes, int n_in,
                              void* d_out, int out_size) {
    const float* x    = (const float*)d_in[0];
    const float* w    = (const float*)d_in[1];
    const float* bias = (const float*)d_in[2];
    float* out = (float*)d_out;

    cudaFuncSetAttribute(conv_mma_kernel,
                         cudaFuncAttributeMaxDynamicSharedMemorySize, SMEM_BYTES);

    prep_weights<<<(NTAP * 1024 + 255) / 256, 256>>>(w);
    prep_halos<<<NTILES, 256>>>(x);

    dim3 grid(NTX, NTY, BATCH);
    conv_mma_kernel<<<grid, 256, SMEM_BYTES>>>(bias, out);
}

// round 17
// speedup vs baseline: 1.7622x; 1.1115x over previous
#include <cuda_runtime.h>
#include <cuda_fp16.h>
#include <cstdint>

#define H_IN   224
#define H_OUT  220
#define C_IN   32
#define N_FILT 64
#define KS     5
#define NTAP   25
#define BATCH  16

#define TR 16
#define TC 32
#define HR 20
#define HC 36
#define NLINES (HR * HC)   // 720
#define NTX 7
#define NTY 14

#define ASTRIDE 80
#define A_BYTES (NLINES * ASTRIDE)          // 57600
#define B_TILE  4096
#define B_OFF   A_BYTES
#define SMEM_BYTES (B_OFF + NTAP * B_TILE)  // 160000

__device__ __half g_wf[NTAP * 2048];

// ---------------- helpers ----------------
__device__ __forceinline__ uint32_t smem_u32(const void* p) {
    uint32_t a;
    asm("{ .reg .u64 t; cvta.to.shared.u64 t, %1; cvt.u32.u64 %0, t; }" : "=r"(a) : "l"(p));
    return a;
}
__device__ __forceinline__ void cpa16(uint32_t s, const void* g) {
    asm volatile("cp.async.ca.shared.global [%0], [%1], 16;" :: "r"(s), "l"(g));
}
__device__ __forceinline__ void cp_commit() { asm volatile("cp.async.commit_group;"); }
__device__ __forceinline__ void cp_wait0()  { asm volatile("cp.async.wait_group 0;"); }

__device__ __forceinline__ void ldsm4(uint32_t* r, uint32_t a) {
    asm volatile("ldmatrix.sync.aligned.m8n8.x4.shared.b16 {%0,%1,%2,%3}, [%4];"
                 : "=r"(r[0]), "=r"(r[1]), "=r"(r[2]), "=r"(r[3]) : "r"(a));
}
__device__ __forceinline__ void ldsv4(uint32_t* r, uint32_t a) {
    asm volatile("ld.shared.v4.u32 {%0,%1,%2,%3}, [%4];"
                 : "=r"(r[0]), "=r"(r[1]), "=r"(r[2]), "=r"(r[3]) : "r"(a));
}
__device__ __forceinline__ void mma16816(float* d, const uint32_t* a,
                                         uint32_t b0, uint32_t b1) {
    asm volatile(
        "mma.sync.aligned.m16n8k16.row.col.f32.f16.f16.f32 "
        "{%0,%1,%2,%3}, {%4,%5,%6,%7}, {%8,%9}, {%0,%1,%2,%3};"
        : "+f"(d[0]), "+f"(d[1]), "+f"(d[2]), "+f"(d[3])
        : "r"(a[0]), "r"(a[1]), "r"(a[2]), "r"(a[3]), "r"(b0), "r"(b1));
}
__device__ __forceinline__ void sts32(uint32_t a, uint32_t v) {
    asm volatile("st.shared.b32 [%0], %1;" :: "r"(a), "r"(v));
}

// ---------------- prep: weights -> fp16 in mma-fragment order ----------------
__global__ void prep_weights(const float* __restrict__ w) {
    int idx = blockIdx.x * blockDim.x + threadIdx.x;
    if (idx >= NTAP * 1024) return;
    int tap = idx >> 10;
    int rem = idx & 1023;
    int grp  = rem >> 7;
    int lane = (rem >> 2) & 31;
    int r    = rem & 3;
    int ks = grp >> 2, np = grp & 3;
    int c = ks * 16 + (lane & 3) * 2 + ((r & 1) ? 8 : 0);
    int f = np * 16 + (lane >> 2)   + ((r & 2) ? 8 : 0);
    __half h0 = __float2half(w[(f * C_IN + c    ) * (KS * KS) + tap]);
    __half h1 = __float2half(w[(f * C_IN + c + 1) * (KS * KS) + tap]);
    __half2* dst = reinterpret_cast<__half2*>(g_wf + (size_t)tap * 2048);
    dst[rem] = __halves2half2(h0, h1);
}

// ---------------- main kernel ----------------
__global__ __launch_bounds__(256, 1)
void conv_mma_kernel(const float* __restrict__ x,
                     const float* __restrict__ bias,
                     float* __restrict__ out)
{
    extern __shared__ __align__(128) char smem[];
    const uint32_t sb = smem_u32(smem);

    const int tid = threadIdx.x;
    const int wid = tid >> 5, lid = tid & 31;
    const int g = lid >> 2, c4 = lid & 3;

    const int x0 = blockIdx.x * TC;
    const int y0 = blockIdx.y * TR;
    const int b  = blockIdx.z;

    // ---- stage ALL B tiles (100KB, async) ----
    #pragma unroll
    for (int j = 0; j < 25; ++j)
        cpa16(sb + B_OFF + (tid + j * 256) * 16, g_wf + ((size_t)tid + j * 256) * 8);
    cp_commit();

    // ---- build A halo: chunk-XOR swizzled, conflict-reduced STS.32 ----
    {
        const float* xb = x + (size_t)b * C_IN * H_IN * H_IN;
        #pragma unroll 1
        for (int j = 0; j < 3; ++j) {
            int line = tid + j * 256;
            if (line < NLINES) {
                int hy = line / HC, hx = line - hy * HC;
                int gy = y0 + hy, gx = x0 + hx;
                const bool ok = (gy < H_IN) && (gx < H_IN);
                const float* p = xb + (size_t)gy * H_IN + gx;
                const uint32_t lbase = sb + line * ASTRIDE;
                const uint32_t swl = (((uint32_t)line >> 3) & 3) << 4;
                #pragma unroll
                for (int cp = 0; cp < 16; ++cp) {
                    float v0 = ok ? p[(size_t)(2 * cp    ) * (H_IN * H_IN)] : 0.0f;
                    float v1 = ok ? p[(size_t)(2 * cp + 1) * (H_IN * H_IN)] : 0.0f;
                    __half2 h = __floats2half2_rn(v0, v1);
                    uint32_t addr = lbase
                                  + (((((uint32_t)cp >> 2) << 4)) ^ swl)
                                  + (cp & 3) * 4;
                    sts32(addr, *reinterpret_cast<uint32_t*>(&h));
                }
            }
        }
    }
    cp_wait0();
    __syncthreads();      // the ONLY barrier

    float acc[4][8][4];
    #pragma unroll
    for (int mb = 0; mb < 4; ++mb)
        #pragma unroll
        for (int ns = 0; ns < 8; ++ns)
            #pragma unroll
            for (int q = 0; q < 4; ++q) acc[mb][ns][q] = 0.0f;

    const int lrow = lid & 15;
    const int lcol = lid >> 4;
    const uint32_t b_base0 = sb + B_OFF + lid * 16;

    // load fragments of ONE halo row (both kk, both x-halves) with swizzle
    auto load_row = [&](uint32_t f[2][2][4], int line_top) {
        #pragma unroll
        for (int kk = 0; kk < 2; ++kk) {
            #pragma unroll
            for (int xh = 0; xh < 2; ++xh) {
                const int ln = line_top + xh * 16 + lrow;
                const uint32_t sw = (((uint32_t)ln >> 3) & 3);
                const uint32_t addr = sb + (uint32_t)ln * ASTRIDE
                                    + ((((uint32_t)(kk * 2 + lcol)) ^ sw) << 4);
                ldsm4(f[kk][xh], addr);
            }
        }
    };

    uint32_t fA[2][2][2][4];    // [parity][kk][xhalf][4]

    #pragma unroll 1
    for (int kw = 0; kw < 5; ++kw) {
        const int base0 = 2 * wid * HC + kw;
        load_row(fA[0], base0);            // halo row 2w
        load_row(fA[1], base0 + HC);       // halo row 2w+1

        #pragma unroll
        for (int kh = 0; kh < 5; ++kh) {
            const int p0 = kh & 1;          // frag slot holding halo row 2w+kh
            const int p1 = p0 ^ 1;          // slot holding halo row 2w+kh+1
            const uint32_t b_t = b_base0 + (uint32_t)(kh * 5 + kw) * B_TILE;

            uint32_t bq[2][4][4];
            #pragma unroll
            for (int kk = 0; kk < 2; ++kk)
                #pragma unroll
                for (int np = 0; np < 4; ++np)
                    ldsv4(bq[kk][np], b_t + (kk * 4 + np) * 512);

            #pragma unroll
            for (int kk = 0; kk < 2; ++kk) {
                #pragma unroll
                for (int np = 0; np < 4; ++np) {
                    mma16816(acc[0][2 * np + 0], fA[p0][kk][0], bq[kk][np][0], bq[kk][np][1]);
                    mma16816(acc[0][2 * np + 1], fA[p0][kk][0], bq[kk][np][2], bq[kk][np][3]);
                    mma16816(acc[1][2 * np + 0], fA[p0][kk][1], bq[kk][np][0], bq[kk][np][1]);
                    mma16816(acc[1][2 * np + 1], fA[p0][kk][1], bq[kk][np][2], bq[kk][np][3]);
                    mma16816(acc[2][2 * np + 0], fA[p1][kk][0], bq[kk][np][0], bq[kk][np][1]);
                    mma16816(acc[2][2 * np + 1], fA[p1][kk][0], bq[kk][np][2], bq[kk][np][3]);
                    mma16816(acc[3][2 * np + 0], fA[p1][kk][1], bq[kk][np][0], bq[kk][np][1]);
                    mma16816(acc[3][2 * np + 1], fA[p1][kk][1], bq[kk][np][2], bq[kk][np][3]);
                }
            }

            if (kh < 4)
                load_row(fA[p0], base0 + (kh + 2) * HC);   // next new row into freed slot
        }
    }

    // ---- epilogue (r10-proven) ----
    float bv[8][2];
    #pragma unroll
    for (int ns = 0; ns < 8; ++ns) {
        bv[ns][0] = bias[ns * 8 + 2 * c4];
        bv[ns][1] = bias[ns * 8 + 2 * c4 + 1];
    }

    #pragma unroll
    for (int mb = 0; mb < 4; ++mb) {
        const int oy = y0 + 2 * wid + (mb >> 1);
        if (oy >= H_OUT) continue;
        #pragma unroll
        for (int h = 0; h < 2; ++h) {
            const int ox = x0 + (mb & 1) * 16 + h * 8 + g;
            if (ox >= H_OUT) continue;
            size_t base = (((size_t)b * N_FILT) * H_OUT + oy) * H_OUT + ox;
            #pragma unroll
            for (int ns = 0; ns < 8; ++ns) {
                int f = ns * 8 + 2 * c4;
                out[base + (size_t)f * H_OUT * H_OUT] =
                    acc[mb][ns][2 * h + 0] + bv[ns][0];
                out[base + (size_t)(f + 1) * H_OUT * H_OUT] =
                    acc[mb][ns][2 * h + 1] + bv[ns][1];
            }
        }
    }
}

extern "C" void kernel_launch(void* const* d_in, const int* in_sizes, int n_in,
                              void* d_out, int out_size) {
    const float* x    = (const float*)d_in[0];
    const float* w    = (const float*)d_in[1];
    const float* bias = (const float*)d_in[2];
    float* out = (float*)d_out;

    cudaFuncSetAttribute(conv_mma_kernel,
                         cudaFuncAttributeMaxDynamicSharedMemorySize, SMEM_BYTES);

    prep_weights<<<(NTAP * 1024 + 255) / 256, 256>>>(w);

    dim3 grid(NTX, NTY, BATCH);
    conv_mma_kernel<<<grid, 256, SMEM_BYTES>>>(x, bias, out);
}